// round 10
// baseline (speedup 1.0000x reference)
#include <cuda_runtime.h>

// Shapes (fixed per reference setup_inputs)
#define L_DIM 4
#define B_DIM 8
#define C_DIM 256
#define HW 4096                 // 64*64 spatial
#define QROW (HW / 4)           // 1024 float4 per row
#define NROWS (L_DIM * B_DIM * C_DIM)   // 8192

#define NCHUNK 4                // chunks of 2 batches; 2048 rows = 32 MiB each
#define GBLOCKS 1024            // gap blocks per chunk (2 rows/block)
#define SBLOCKS 2048            // scale blocks per chunk (1 row/block)

// Scratch (no allocations allowed)
__device__ float g_gap[NROWS];
__device__ float g_attn[NROWS];

__device__ __forceinline__ float sum4(float4 v) { return (v.x + v.y) + (v.z + v.w); }

// chunk-local even index -> global row. Chunk rows: l in 0..3, b in
// {b_base, b_base+1}, c in 0..255.  row = l*2048 + b*256 + c
__device__ __forceinline__ int chunk_row_from_idx(int idx, int b_base) {
    const int l   = idx >> 9;              // /512
    const int rem = idx & 511;
    const int b   = b_base + (rem >> 8);
    const int c   = rem & 255;
    return l * (B_DIM * C_DIM) + b * C_DIM + c;
}

// ---------------------------------------------------------------------------
// Kernel 1: GAP over one chunk — 2 rows per block, 8 front-loaded LDG.128.
// Reads populate L2 for the chunk's scale pass.
// ---------------------------------------------------------------------------
__global__ __launch_bounds__(256) void gap_kernel(const float4* __restrict__ in4,
                                                  int b_base) {
    const int r0 = chunk_row_from_idx(2 * blockIdx.x, b_base);
    const int r1 = r0 + 1;                 // same (l,b), c+1
    const float4* p0 = in4 + (size_t)r0 * QROW;
    const float4* p1 = in4 + (size_t)r1 * QROW;
    const int t = threadIdx.x;

    float4 a0 = p0[t], a1 = p0[t + 256], a2 = p0[t + 512], a3 = p0[t + 768];
    float4 b0 = p1[t], b1 = p1[t + 256], b2 = p1[t + 512], b3 = p1[t + 768];

    float sA = sum4(a0) + sum4(a1) + sum4(a2) + sum4(a3);
    float sB = sum4(b0) + sum4(b1) + sum4(b2) + sum4(b3);

    #pragma unroll
    for (int off = 16; off > 0; off >>= 1) {
        sA += __shfl_xor_sync(0xffffffffu, sA, off);
        sB += __shfl_xor_sync(0xffffffffu, sB, off);
    }

    __shared__ float wsum[2][8];
    if ((t & 31) == 0) {
        wsum[0][t >> 5] = sA;
        wsum[1][t >> 5] = sB;
    }
    __syncthreads();

    if (t < 2) {
        float r = 0.f;
        #pragma unroll
        for (int k = 0; k < 8; k++) r += wsum[t][k];
        g_gap[r0 + t] = r * (1.0f / (float)HW);
    }
}

// ---------------------------------------------------------------------------
// Kernel 2: attn for one chunk (2 batches). 2 blocks, thread d owns channel d.
// ---------------------------------------------------------------------------
__global__ __launch_bounds__(256) void attn_kernel(const float* __restrict__ Wlin,
                                                   int b_base) {
    const int b = b_base + blockIdx.x;
    const int d = threadIdx.x;

    __shared__ float gap_sh[L_DIM][C_DIM];
    #pragma unroll
    for (int l = 0; l < L_DIM; ++l)
        gap_sh[l][d] = g_gap[l * (B_DIM * C_DIM) + b * C_DIM + d];
    __syncthreads();

    float acc0 = 0.f, acc1 = 0.f, acc2 = 0.f, acc3 = 0.f;
    const float* wrow = Wlin + (size_t)d * C_DIM;   // W[d, :]
    #pragma unroll 8
    for (int c = 0; c < C_DIM; ++c) {
        float w = __ldg(&wrow[c]);
        acc0 = fmaf(gap_sh[0][c], w, acc0);
        acc1 = fmaf(gap_sh[1][c], w, acc1);
        acc2 = fmaf(gap_sh[2][c], w, acc2);
        acc3 = fmaf(gap_sh[3][c], w, acc3);
    }

    float m = fmaxf(fmaxf(acc0, acc1), fmaxf(acc2, acc3));
    float e0 = __expf(acc0 - m);
    float e1 = __expf(acc1 - m);
    float e2 = __expf(acc2 - m);
    float e3 = __expf(acc3 - m);
    float inv = 1.0f / (e0 + e1 + e2 + e3);

    const int base = b * C_DIM + d;
    g_attn[0 * (B_DIM * C_DIM) + base] = e0 * inv;
    g_attn[1 * (B_DIM * C_DIM) + base] = e1 * inv;
    g_attn[2 * (B_DIM * C_DIM) + base] = e2 * inv;
    g_attn[3 * (B_DIM * C_DIM) + base] = e3 * inv;
}

// ---------------------------------------------------------------------------
// Kernel 3: scale for one chunk — prologue-free copy-multiply.
// 1 row/block, 2048 blocks: ~24 regs -> 8 blocks/SM, fully latency-hidden.
// Reads hit L2 (chunk resident from gap). Default write-back stores (proven).
// ---------------------------------------------------------------------------
__global__ __launch_bounds__(256) void scale_kernel(const float4* __restrict__ in4,
                                                    float4* __restrict__ out4,
                                                    int b_base) {
    const int row = chunk_row_from_idx(blockIdx.x, b_base);
    const float a = g_attn[row];
    const float4* p = in4 + (size_t)row * QROW;
    float4*       q = out4 + (size_t)row * QROW;
    const int t = threadIdx.x;

    float4 v0 = p[t];
    float4 v1 = p[t + 256];
    float4 v2 = p[t + 512];
    float4 v3 = p[t + 768];

    v0.x *= a; v0.y *= a; v0.z *= a; v0.w *= a;
    v1.x *= a; v1.y *= a; v1.z *= a; v1.w *= a;
    v2.x *= a; v2.y *= a; v2.z *= a; v2.w *= a;
    v3.x *= a; v3.y *= a; v3.z *= a; v3.w *= a;

    q[t]       = v0;
    q[t + 256] = v1;
    q[t + 512] = v2;
    q[t + 768] = v3;
}

// ---------------------------------------------------------------------------
extern "C" void kernel_launch(void* const* d_in, const int* in_sizes, int n_in,
                              void* d_out, int out_size) {
    const float4* in4  = (const float4*)d_in[0];
    const float*  Wlin = (const float*)d_in[1];
    float4*       out4 = (float4*)d_out;

    // Per 2-batch chunk: gap (reads chunk into L2) -> tiny attn -> scale
    // (re-reads from L2, writes DRAM). Chunk + write stream = 64 MiB << L2.
    for (int ci = 0; ci < NCHUNK; ci++) {
        const int b_base = 2 * ci;
        gap_kernel<<<GBLOCKS, 256>>>(in4, b_base);
        attn_kernel<<<2, 256>>>(Wlin, b_base);
        scale_kernel<<<SBLOCKS, 256>>>(in4, out4, b_base);
    }
}

// round 11
// speedup vs baseline: 3.0927x; 3.0927x over previous
#include <cuda_runtime.h>

// Shapes (fixed per reference setup_inputs)
#define L_DIM 4
#define B_DIM 8
#define C_DIM 256
#define HW 4096                 // 64*64 spatial
#define QROW (HW / 4)           // 1024 float4 per row
#define NROWS (L_DIM * B_DIM * C_DIM)   // 8192

#define NCHUNK 4                // chunks of 2 batches; 2048 rows = 32 MiB each
#define SROWS 2048              // rows per chunk (scale: 1 row/block)
#define GBLK 1024               // gap blocks per chunk (2 rows/block)

// Scratch (no allocations allowed)
__device__ float g_gap[NROWS];

__device__ __forceinline__ float sum4(float4 v) { return (v.x + v.y) + (v.z + v.w); }

// chunk-local index -> global row. Chunk rows: l in 0..3, b in
// {b_base, b_base+1}, c in 0..255.  row = l*2048 + b*256 + c
__device__ __forceinline__ int chunk_row_from_idx(int idx, int b_base) {
    const int l   = idx >> 9;              // /512
    const int rem = idx & 511;
    const int b   = b_base + (rem >> 8);
    const int c   = rem & 255;
    return l * (B_DIM * C_DIM) + b * C_DIM + c;
}

// ---------------------------------------------------------------------------
// Fused pipeline kernel.
// mode 0: gap-only (grid GBLK)           — chunk gap_b_base
// mode 1: scale+gap (grid SROWS+GBLK)    — scale chunk scale_b_base,
//         gap chunk gap_b_base, interleaved 2 scale : 1 gap by bid%3
// mode 2: scale-only (grid SROWS)        — chunk scale_b_base
//
// gap path:  2 rows/block, 8 front-loaded LDG.128 -> mean -> g_gap
// scale path: 1 row/block; 4 LDG.128 issued first; slim fused-attn prologue
//   (coalesced W/gap reads, 1 __syncthreads, redundant per-thread softmax);
//   default write-back stores (proven fastest).
// ---------------------------------------------------------------------------
__global__ __launch_bounds__(256) void sffm_kernel(const float4* __restrict__ in4,
                                                   const float*  __restrict__ Wlin,
                                                   float4* __restrict__ out4,
                                                   int scale_b_base,
                                                   int gap_b_base,
                                                   int mode) {
    const int t = threadIdx.x;
    __shared__ float sh[4][8];

    int role, j;   // role 0 = gap, 1 = scale
    if (mode == 1) {
        const int g = blockIdx.x % 3;
        const int q = blockIdx.x / 3;
        if (g == 2) { role = 0; j = q; }           // gap block    (0..GBLK-1)
        else        { role = 1; j = q * 2 + g; }   // scale block  (0..SROWS-1)
    } else if (mode == 0) {
        role = 0; j = blockIdx.x;
    } else {
        role = 1; j = blockIdx.x;
    }

    if (role == 0) {
        // ---------------- GAP: 2 rows ----------------
        const int r0 = chunk_row_from_idx(2 * j, gap_b_base);
        const int r1 = r0 + 1;                      // same (l,b), c+1
        const float4* p0 = in4 + (size_t)r0 * QROW;
        const float4* p1 = in4 + (size_t)r1 * QROW;

        float4 a0 = p0[t], a1 = p0[t + 256], a2 = p0[t + 512], a3 = p0[t + 768];
        float4 b0 = p1[t], b1 = p1[t + 256], b2 = p1[t + 512], b3 = p1[t + 768];

        float sA = sum4(a0) + sum4(a1) + sum4(a2) + sum4(a3);
        float sB = sum4(b0) + sum4(b1) + sum4(b2) + sum4(b3);

        #pragma unroll
        for (int off = 16; off > 0; off >>= 1) {
            sA += __shfl_xor_sync(0xffffffffu, sA, off);
            sB += __shfl_xor_sync(0xffffffffu, sB, off);
        }
        if ((t & 31) == 0) {
            sh[0][t >> 5] = sA;
            sh[1][t >> 5] = sB;
        }
        __syncthreads();
        if (t < 2) {
            float r = 0.f;
            #pragma unroll
            for (int k = 0; k < 8; k++) r += sh[t][k];
            g_gap[r0 + t] = r * (1.0f / (float)HW);
        }
    } else {
        // ---------------- SCALE: 1 row, fused attn ----------------
        const int row = chunk_row_from_idx(j, scale_b_base);
        const float4* p = in4 + (size_t)row * QROW;
        float4*       q = out4 + (size_t)row * QROW;

        // issue the 4 big loads first (L2 hits for the resident chunk)
        float4 v0 = p[t];
        float4 v1 = p[t + 256];
        float4 v2 = p[t + 512];
        float4 v3 = p[t + 768];

        // attn prologue: row = l*2048 + b*256 + d
        const int l = row >> 11;
        const int b = (row >> 8) & 7;
        const int d = row & 255;

        const float wt = __ldg(&Wlin[d * C_DIM + t]);       // coalesced
        float s0 = __ldg(&g_gap[0 * (B_DIM * C_DIM) + b * C_DIM + t]) * wt;
        float s1 = __ldg(&g_gap[1 * (B_DIM * C_DIM) + b * C_DIM + t]) * wt;
        float s2 = __ldg(&g_gap[2 * (B_DIM * C_DIM) + b * C_DIM + t]) * wt;
        float s3 = __ldg(&g_gap[3 * (B_DIM * C_DIM) + b * C_DIM + t]) * wt;

        #pragma unroll
        for (int off = 16; off > 0; off >>= 1) {
            s0 += __shfl_xor_sync(0xffffffffu, s0, off);
            s1 += __shfl_xor_sync(0xffffffffu, s1, off);
            s2 += __shfl_xor_sync(0xffffffffu, s2, off);
            s3 += __shfl_xor_sync(0xffffffffu, s3, off);
        }
        if ((t & 31) == 0) {
            sh[0][t >> 5] = s0;
            sh[1][t >> 5] = s1;
            sh[2][t >> 5] = s2;
            sh[3][t >> 5] = s3;
        }
        __syncthreads();

        // every thread finishes the reduction + softmax redundantly (no 2nd sync)
        float sc0 = 0.f, sc1 = 0.f, sc2 = 0.f, sc3 = 0.f;
        #pragma unroll
        for (int k = 0; k < 8; k++) {
            sc0 += sh[0][k];
            sc1 += sh[1][k];
            sc2 += sh[2][k];
            sc3 += sh[3][k];
        }
        const float m = fmaxf(fmaxf(sc0, sc1), fmaxf(sc2, sc3));
        const float e0 = __expf(sc0 - m);
        const float e1 = __expf(sc1 - m);
        const float e2 = __expf(sc2 - m);
        const float e3 = __expf(sc3 - m);
        const float inv = 1.0f / (e0 + e1 + e2 + e3);
        const float el = (l == 0) ? e0 : (l == 1) ? e1 : (l == 2) ? e2 : e3;
        const float a = el * inv;

        v0.x *= a; v0.y *= a; v0.z *= a; v0.w *= a;
        v1.x *= a; v1.y *= a; v1.z *= a; v1.w *= a;
        v2.x *= a; v2.y *= a; v2.z *= a; v2.w *= a;
        v3.x *= a; v3.y *= a; v3.z *= a; v3.w *= a;

        q[t]       = v0;
        q[t + 256] = v1;
        q[t + 512] = v2;
        q[t + 768] = v3;
    }
}

// ---------------------------------------------------------------------------
extern "C" void kernel_launch(void* const* d_in, const int* in_sizes, int n_in,
                              void* d_out, int out_size) {
    const float4* in4  = (const float4*)d_in[0];
    const float*  Wlin = (const float*)d_in[1];
    float4*       out4 = (float4*)d_out;

    // Software pipeline over 2-batch chunks:
    //   K0:        gap(c0)
    //   K1..K3:    scale(c_i) + gap(c_{i+1})   — co-scheduled in one launch
    //   K4:        scale(c3)
    // scale(c_i) reads hit L2 (chunk loaded by the previous launch); its
    // DRAM writes overlap with gap(c_{i+1})'s DRAM reads.
    sffm_kernel<<<GBLK, 256>>>(in4, Wlin, out4, 0, 0, 0);
    for (int ci = 0; ci < NCHUNK - 1; ci++)
        sffm_kernel<<<SROWS + GBLK, 256>>>(in4, Wlin, out4, 2 * ci, 2 * (ci + 1), 1);
    sffm_kernel<<<SROWS, 256>>>(in4, Wlin, out4, 2 * (NCHUNK - 1), 0, 2);
}